// round 1
// baseline (speedup 1.0000x reference)
#include <cuda_runtime.h>

#define B_N 16
#define K_N 20
#define H_N 256
#define W_N 256
#define HW_N 65536
#define RAD 4
#define PADW 264     // 256 + 2*RAD
#define STRIP_H 64
#define PADH 72      // STRIP_H + 2*RAD
#define NSTRIP 4
#define NPART (B_N*NSTRIP)   // 64 partials per class

__device__ float g_stats[B_N * K_N * 4];
__device__ float g_num[K_N * NPART];
__device__ float g_den[K_N * NPART];

// ---------------------------------------------------------------------------
// Kernel 1: per-(b,k) sums:  sum(labels), sum(labels*x_c) for c=0..2
// ---------------------------------------------------------------------------
__global__ __launch_bounds__(256) void stats_kernel(const float* __restrict__ labels,
                                                    const float* __restrict__ inputs) {
    const int k = blockIdx.x, b = blockIdx.y, t = threadIdx.x;
    const float4* L  = (const float4*)(labels + (size_t)(b * K_N + k) * HW_N);
    const float4* X0 = (const float4*)(inputs + (size_t)(b * 3) * HW_N);
    const float4* X1 = X0 + (HW_N / 4);
    const float4* X2 = X1 + (HW_N / 4);

    float sL = 0.f, s0 = 0.f, s1 = 0.f, s2 = 0.f;
    for (int i = t; i < HW_N / 4; i += 256) {
        float4 l = L[i], a = X0[i], c = X1[i], d = X2[i];
        sL += (l.x + l.y) + (l.z + l.w);
        s0 = fmaf(l.x, a.x, fmaf(l.y, a.y, fmaf(l.z, a.z, fmaf(l.w, a.w, s0))));
        s1 = fmaf(l.x, c.x, fmaf(l.y, c.y, fmaf(l.z, c.z, fmaf(l.w, c.w, s1))));
        s2 = fmaf(l.x, d.x, fmaf(l.y, d.y, fmaf(l.z, d.z, fmaf(l.w, d.w, s2))));
    }
    #pragma unroll
    for (int o = 16; o; o >>= 1) {
        sL += __shfl_down_sync(0xffffffffu, sL, o);
        s0 += __shfl_down_sync(0xffffffffu, s0, o);
        s1 += __shfl_down_sync(0xffffffffu, s1, o);
        s2 += __shfl_down_sync(0xffffffffu, s2, o);
    }
    __shared__ float red[8][4];
    const int wid = t >> 5, lane = t & 31;
    if (lane == 0) { red[wid][0] = sL; red[wid][1] = s0; red[wid][2] = s1; red[wid][3] = s2; }
    __syncthreads();
    if (t == 0) {
        float a0 = 0, a1 = 0, a2 = 0, a3 = 0;
        #pragma unroll
        for (int w = 0; w < 8; w++) { a0 += red[w][0]; a1 += red[w][1]; a2 += red[w][2]; a3 += red[w][3]; }
        float* st = &g_stats[(b * K_N + k) * 4];
        st[0] = a0; st[1] = a1; st[2] = a2; st[3] = a3;
    }
}

// ---------------------------------------------------------------------------
// Kernel 2: fused weights + separable 9x9 blur (two fields) + reduction.
// Block = 128 threads = one (b,k,strip). Each thread owns 2 output columns.
// Horizontal blur via smem row buffer (double-buffered, float2 loads),
// vertical blur via 9-deep register ring with static indices.
// ---------------------------------------------------------------------------
__global__ __launch_bounds__(128) void main_kernel(const float* __restrict__ labels,
                                                   const float* __restrict__ inputs) {
    const int t = threadIdx.x;
    const int s = blockIdx.x;   // strip 0..3
    const int k = blockIdx.y;
    const int b = blockIdx.z;

    // g(d) = exp(-d^2 / (2*SIGMA1^2)), SIGMA1=5  -> literal immediates in SASS
    constexpr float G[9] = {0.72614903f, 0.83527021f, 0.92311635f, 0.98019867f, 1.0f,
                            0.98019867f, 0.92311635f, 0.83527021f, 0.72614903f};

    __shared__ float sW[2][PADW];
    __shared__ float sLW[2][PADW];

    const float* st = &g_stats[(b * K_N + k) * 4];
    // class_mean_c = sumX_c / (sumL + 1e-5*HW)
    const float inv = 1.0f / (st[0] + 0.65536f);
    const float cm0 = st[1] * inv, cm1 = st[2] * inv, cm2 = st[3] * inv;

    const float* lab = labels + (size_t)(b * K_N + k) * HW_N;
    const float* xp0 = inputs + (size_t)(b * 3) * HW_N;
    const float* xp1 = xp0 + HW_N;
    const float* xp2 = xp1 + HW_N;

    const int row0 = s * STRIP_H - RAD;   // global row of padded row 0
    const int oc0 = 2 * t;                // this thread's two output columns

    float rw0[9], rw1[9], rl0[9], rl1[9]; // vertical ring (h-blurred rows)
    float numAcc = 0.f, denAcc = 0.f;

    for (int prb = 0; prb < PADH; prb += 9) {
        #pragma unroll
        for (int u = 0; u < 9; u++) {
            const int pr  = prb + u;
            const int gr  = row0 + pr;
            const int buf = pr & 1;
            const bool rowOK = ((unsigned)gr < (unsigned)H_N);
            const int rowOff = gr * W_N;

            // --- compute w = exp(-diff^2), lw = l*w for padded columns ---
            for (int pc = t; pc < PADW; pc += 128) {
                const int gc = pc - RAD;
                float w = 0.f, lw = 0.f;
                if (rowOK && ((unsigned)gc < (unsigned)W_N)) {
                    const int idx  = rowOff + gc;
                    const float l  = __ldg(lab + idx);
                    const float a0 = __ldg(xp0 + idx) - cm0;
                    const float a1 = __ldg(xp1 + idx) - cm1;
                    const float a2 = __ldg(xp2 + idx) - cm2;
                    const float d  = fmaf(a0, a0, fmaf(a1, a1, a2 * a2));
                    w  = __expf(-d * d);
                    lw = l * w;
                }
                sW[buf][pc]  = w;
                sLW[buf][pc] = lw;
            }
            __syncthreads();

            // --- horizontal 9-tap for output cols oc0, oc0+1 ---
            {
                const float2* w2 = (const float2*)&sW[buf][oc0];
                const float2* l2 = (const float2*)&sLW[buf][oc0];
                float vw[10], vl[10];
                #pragma unroll
                for (int i = 0; i < 5; i++) {
                    float2 a = w2[i]; vw[2 * i] = a.x; vw[2 * i + 1] = a.y;
                    float2 c = l2[i]; vl[2 * i] = c.x; vl[2 * i + 1] = c.y;
                }
                float wh0 = vw[0] * G[0], wh1 = vw[1] * G[0];
                float lh0 = vl[0] * G[0], lh1 = vl[1] * G[0];
                #pragma unroll
                for (int j = 1; j < 9; j++) {
                    wh0 = fmaf(vw[j],     G[j], wh0);
                    wh1 = fmaf(vw[j + 1], G[j], wh1);
                    lh0 = fmaf(vl[j],     G[j], lh0);
                    lh1 = fmaf(vl[j + 1], G[j], lh1);
                }
                rw0[u] = wh0; rw1[u] = wh1; rl0[u] = lh0; rl1[u] = lh1;  // ring slot pr%9 == u
            }

            // --- vertical 9-tap completes output row y = pr-8 ---
            if (pr >= 8) {
                float oW0 = 0.f, oW1 = 0.f, oL0 = 0.f, oL1 = 0.f;
                #pragma unroll
                for (int j = 0; j < 9; j++) {
                    const int slot = (u + 1 + j) % 9;   // (pr-8+j) % 9, static
                    oW0 = fmaf(rw0[slot], G[j], oW0);
                    oW1 = fmaf(rw1[slot], G[j], oW1);
                    oL0 = fmaf(rl0[slot], G[j], oL0);
                    oL1 = fmaf(rl1[slot], G[j], oL1);
                }
                const int gor = s * STRIP_H + pr - 8;
                const float2 lp = __ldg((const float2*)(lab + gor * W_N + oc0));
                numAcc = fmaf(lp.x, oL0, numAcc);
                numAcc = fmaf(lp.y, oL1, numAcc);
                denAcc = fmaf(lp.x, oW0, denAcc);
                denAcc = fmaf(lp.y, oW1, denAcc);
            }
        }
    }

    // --- block reduction (fixed order -> deterministic) ---
    #pragma unroll
    for (int o = 16; o; o >>= 1) {
        numAcc += __shfl_down_sync(0xffffffffu, numAcc, o);
        denAcc += __shfl_down_sync(0xffffffffu, denAcc, o);
    }
    __shared__ float rn[4], rd[4];
    if ((t & 31) == 0) { rn[t >> 5] = numAcc; rd[t >> 5] = denAcc; }
    __syncthreads();
    if (t == 0) {
        const float n = (rn[0] + rn[1]) + (rn[2] + rn[3]);
        const float d = (rd[0] + rd[1]) + (rd[2] + rd[3]);
        const int idx = (k * B_N + b) * NSTRIP + s;
        g_num[idx] = n;
        g_den[idx] = d;
    }
}

// ---------------------------------------------------------------------------
// Kernel 3: final deterministic reduction -> scalar loss
// ---------------------------------------------------------------------------
__global__ void finish_kernel(float* __restrict__ out) {
    __shared__ float sv[K_N];
    const int t = threadIdx.x;
    if (t < K_N) {
        float n = 0.f, d = 0.f;
        for (int i = 0; i < NPART; i++) {
            n += g_num[t * NPART + i];
            d += g_den[t * NPART + i];
        }
        sv[t] = fabsf(n / (d + 1e-6f));
    }
    __syncthreads();
    if (t == 0) {
        float loss = 0.f;
        for (int i = 0; i < K_N; i++) loss += sv[i];
        out[0] = (float)K_N - loss;
    }
}

// ---------------------------------------------------------------------------
extern "C" void kernel_launch(void* const* d_in, const int* in_sizes, int n_in,
                              void* d_out, int out_size) {
    (void)n_in; (void)out_size;
    const float* labels;
    const float* inputs;
    if (in_sizes[0] == B_N * K_N * HW_N) {
        labels = (const float*)d_in[0];
        inputs = (const float*)d_in[1];
    } else {
        labels = (const float*)d_in[1];
        inputs = (const float*)d_in[0];
    }
    float* out = (float*)d_out;

    stats_kernel<<<dim3(K_N, B_N), 256>>>(labels, inputs);
    main_kernel<<<dim3(NSTRIP, K_N, B_N), 128>>>(labels, inputs);
    finish_kernel<<<1, 32>>>(out);
}

// round 2
// speedup vs baseline: 1.7234x; 1.7234x over previous
#include <cuda_runtime.h>

#define B_N 16
#define K_N 20
#define H_N 256
#define W_N 256
#define HW_N 65536
#define RAD 4
#define PADW 264     // 256 + 2*RAD
#define STRIP_H 64
#define PADH 72      // STRIP_H + 2*RAD (divisible by 9)
#define NSTRIP 4
#define NPART (B_N*NSTRIP)   // 64 partials per class
#define KG 4                 // k's per stats block
#define CH 8                 // HW chunks in stats

__device__ float g_stats4[B_N * K_N * CH * 4];
__device__ float g_num[K_N * NPART];
__device__ float g_den[K_N * NPART];

// ---------------------------------------------------------------------------
// Kernel 1: per-(b,k) partial sums over an HW chunk:
//   sum(labels), sum(labels*x_c) c=0..2.  4 k's per block to amortize x loads.
// ---------------------------------------------------------------------------
__global__ __launch_bounds__(256) void stats_kernel(const float* __restrict__ labels,
                                                    const float* __restrict__ inputs) {
    const int kt = blockIdx.x, b = blockIdx.y, ch = blockIdx.z, t = threadIdx.x;
    const int chunk = HW_N / CH;       // 8192 floats
    const int nf4 = chunk / 4;         // 2048 float4

    const float4* X0 = (const float4*)(inputs + (size_t)(b * 3 + 0) * HW_N + ch * chunk);
    const float4* X1 = (const float4*)(inputs + (size_t)(b * 3 + 1) * HW_N + ch * chunk);
    const float4* X2 = (const float4*)(inputs + (size_t)(b * 3 + 2) * HW_N + ch * chunk);
    const float4* L[KG];
    #pragma unroll
    for (int kk = 0; kk < KG; kk++)
        L[kk] = (const float4*)(labels + (size_t)(b * K_N + kt * KG + kk) * HW_N + ch * chunk);

    float acc[KG][4];
    #pragma unroll
    for (int kk = 0; kk < KG; kk++)
        #pragma unroll
        for (int j = 0; j < 4; j++) acc[kk][j] = 0.f;

    for (int i = t; i < nf4; i += 256) {
        const float4 x0 = X0[i], x1 = X1[i], x2 = X2[i];
        #pragma unroll
        for (int kk = 0; kk < KG; kk++) {
            const float4 l = L[kk][i];
            acc[kk][0] += (l.x + l.y) + (l.z + l.w);
            acc[kk][1] = fmaf(l.x, x0.x, fmaf(l.y, x0.y, fmaf(l.z, x0.z, fmaf(l.w, x0.w, acc[kk][1]))));
            acc[kk][2] = fmaf(l.x, x1.x, fmaf(l.y, x1.y, fmaf(l.z, x1.z, fmaf(l.w, x1.w, acc[kk][2]))));
            acc[kk][3] = fmaf(l.x, x2.x, fmaf(l.y, x2.y, fmaf(l.z, x2.z, fmaf(l.w, x2.w, acc[kk][3]))));
        }
    }

    #pragma unroll
    for (int kk = 0; kk < KG; kk++)
        #pragma unroll
        for (int j = 0; j < 4; j++)
            #pragma unroll
            for (int o = 16; o; o >>= 1)
                acc[kk][j] += __shfl_down_sync(0xffffffffu, acc[kk][j], o);

    __shared__ float red[8][16];
    const int wid = t >> 5, lane = t & 31;
    if (lane == 0) {
        #pragma unroll
        for (int kk = 0; kk < KG; kk++)
            #pragma unroll
            for (int j = 0; j < 4; j++) red[wid][kk * 4 + j] = acc[kk][j];
    }
    __syncthreads();
    if (t < 16) {
        float v = 0.f;
        #pragma unroll
        for (int w = 0; w < 8; w++) v += red[w][t];
        const int k = kt * KG + (t >> 2);
        g_stats4[((b * K_N + k) * CH + ch) * 4 + (t & 3)] = v;
    }
}

// ---------------------------------------------------------------------------
// Kernel 2: adjoint-fused main pass.
//   num_k = sum (l*w) * blur(l),  den_k = sum w * blur(l)
// Only labels are blurred (separable 9x9): h-blur via smem row, v-blur via
// 9-deep register ring with static indices. Weights computed only at output
// pixels. Block = 128 threads = one (b,k,strip); thread owns 2 columns.
// ---------------------------------------------------------------------------
__global__ __launch_bounds__(128) void main_kernel(const float* __restrict__ labels,
                                                   const float* __restrict__ inputs) {
    const int t = threadIdx.x;
    const int s = blockIdx.x;   // strip 0..3
    const int k = blockIdx.y;
    const int b = blockIdx.z;

    // g(d) = exp(-d^2 / (2*5^2)) -> literal immediates (FFMA-imm, rt=1)
    constexpr float G[9] = {0.72614903f, 0.83527021f, 0.92311635f, 0.98019867f, 1.0f,
                            0.98019867f, 0.92311635f, 0.83527021f, 0.72614903f};

    __shared__ float sL[2][PADW];
    __shared__ float sstat[4];

    if (t < 4) {
        float v = 0.f;
        #pragma unroll
        for (int ch = 0; ch < CH; ch++)
            v += g_stats4[((b * K_N + k) * CH + ch) * 4 + t];
        sstat[t] = v;
    }
    __syncthreads();
    // class_mean_c = sumX_c / (sumL + 1e-5*HW)
    const float inv = 1.0f / (sstat[0] + 0.65536f);
    const float cm0 = sstat[1] * inv, cm1 = sstat[2] * inv, cm2 = sstat[3] * inv;

    const float* lab = labels + (size_t)(b * K_N + k) * HW_N;
    const float* xp0 = inputs + (size_t)(b * 3) * HW_N;
    const float* xp1 = xp0 + HW_N;
    const float* xp2 = xp1 + HW_N;

    const int row0 = s * STRIP_H - RAD;   // global row of padded row 0
    const int oc0 = 2 * t;                // this thread's two output columns

    float rb0[9], rb1[9];   // ring: h-blurred labels, cols oc0 / oc0+1
    float ra0[9], ra1[9];   // ring: raw center labels
    float numAcc = 0.f, denAcc = 0.f;

    for (int prb = 0; prb < PADH; prb += 9) {
        #pragma unroll
        for (int u = 0; u < 9; u++) {
            const int pr  = prb + u;
            const int gr  = row0 + pr;
            const int buf = pr & 1;
            const bool rowOK = ((unsigned)gr < (unsigned)H_N);
            const int rowOff = gr * W_N;

            // --- stage labels row into smem (zero-padded) ---
            for (int pc = t; pc < PADW; pc += 128) {
                const int gc = pc - RAD;
                float l = 0.f;
                if (rowOK && ((unsigned)gc < (unsigned)W_N))
                    l = __ldg(lab + rowOff + gc);
                sL[buf][pc] = l;
            }
            __syncthreads();

            // --- horizontal 9-tap for cols oc0, oc0+1 ---
            {
                const float2* p2 = (const float2*)&sL[buf][oc0];
                float v[10];
                #pragma unroll
                for (int i = 0; i < 5; i++) {
                    const float2 a = p2[i]; v[2 * i] = a.x; v[2 * i + 1] = a.y;
                }
                float h0 = v[0] * G[0], h1 = v[1] * G[0];
                #pragma unroll
                for (int j = 1; j < 9; j++) {
                    h0 = fmaf(v[j],     G[j], h0);
                    h1 = fmaf(v[j + 1], G[j], h1);
                }
                rb0[u] = h0; rb1[u] = h1;          // slot pr%9 == u
                ra0[u] = v[4]; ra1[u] = v[5];      // raw labels at own cols
            }

            // --- vertical 9-tap completes output row gor = s*64 + pr - 8 ---
            if (pr >= 8) {
                float B0 = 0.f, B1 = 0.f;
                #pragma unroll
                for (int j = 0; j < 9; j++) {
                    const int slot = (u + 1 + j) % 9;   // (pr-8+j)%9, static
                    B0 = fmaf(rb0[slot], G[j], B0);
                    B1 = fmaf(rb1[slot], G[j], B1);
                }
                const int cs = (u + 5) % 9;             // slot of row gor (pr-4)
                const float l0 = ra0[cs], l1 = ra1[cs];

                const int gor = s * STRIP_H + pr - 8;
                const int idx = gor * W_N + oc0;
                const float2 x0 = __ldg((const float2*)(xp0 + idx));
                const float2 x1 = __ldg((const float2*)(xp1 + idx));
                const float2 x2 = __ldg((const float2*)(xp2 + idx));

                const float a0 = x0.x - cm0, a1 = x1.x - cm1, a2 = x2.x - cm2;
                const float d0 = fmaf(a0, a0, fmaf(a1, a1, a2 * a2));
                const float c0 = x0.y - cm0, c1 = x1.y - cm1, c2 = x2.y - cm2;
                const float d1 = fmaf(c0, c0, fmaf(c1, c1, c2 * c2));
                const float w0 = __expf(-d0 * d0);
                const float w1 = __expf(-d1 * d1);

                numAcc = fmaf(l0 * w0, B0, numAcc);
                numAcc = fmaf(l1 * w1, B1, numAcc);
                denAcc = fmaf(w0, B0, denAcc);
                denAcc = fmaf(w1, B1, denAcc);
            }
        }
    }

    // --- deterministic block reduction ---
    #pragma unroll
    for (int o = 16; o; o >>= 1) {
        numAcc += __shfl_down_sync(0xffffffffu, numAcc, o);
        denAcc += __shfl_down_sync(0xffffffffu, denAcc, o);
    }
    __shared__ float rn[4], rd[4];
    if ((t & 31) == 0) { rn[t >> 5] = numAcc; rd[t >> 5] = denAcc; }
    __syncthreads();
    if (t == 0) {
        const float n = (rn[0] + rn[1]) + (rn[2] + rn[3]);
        const float d = (rd[0] + rd[1]) + (rd[2] + rd[3]);
        const int idx = (k * B_N + b) * NSTRIP + s;
        g_num[idx] = n;
        g_den[idx] = d;
    }
}

// ---------------------------------------------------------------------------
// Kernel 3: final deterministic reduction -> scalar loss
// ---------------------------------------------------------------------------
__global__ void finish_kernel(float* __restrict__ out) {
    __shared__ float sv[K_N];
    const int t = threadIdx.x;
    if (t < K_N) {
        float n = 0.f, d = 0.f;
        for (int i = 0; i < NPART; i++) {
            n += g_num[t * NPART + i];
            d += g_den[t * NPART + i];
        }
        sv[t] = fabsf(n / (d + 1e-6f));
    }
    __syncthreads();
    if (t == 0) {
        float loss = 0.f;
        for (int i = 0; i < K_N; i++) loss += sv[i];
        out[0] = (float)K_N - loss;
    }
}

// ---------------------------------------------------------------------------
extern "C" void kernel_launch(void* const* d_in, const int* in_sizes, int n_in,
                              void* d_out, int out_size) {
    (void)n_in; (void)out_size;
    const float* labels;
    const float* inputs;
    if (in_sizes[0] == B_N * K_N * HW_N) {
        labels = (const float*)d_in[0];
        inputs = (const float*)d_in[1];
    } else {
        labels = (const float*)d_in[1];
        inputs = (const float*)d_in[0];
    }
    float* out = (float*)d_out;

    stats_kernel<<<dim3(K_N / KG, B_N, CH), 256>>>(labels, inputs);
    main_kernel<<<dim3(NSTRIP, K_N, B_N), 128>>>(labels, inputs);
    finish_kernel<<<1, 32>>>(out);
}

// round 3
// speedup vs baseline: 2.4673x; 1.4316x over previous
#include <cuda_runtime.h>

#define B_N 16
#define K_N 20
#define H_N 256
#define W_N 256
#define HW_N 65536
#define RAD 4
#define STRIP_H 64
#define PADH 72      // STRIP_H + 2*RAD (divisible by 9)
#define NSTRIP 4
#define NPART (B_N*NSTRIP)   // 64 partials per class
#define KG 4                 // k's per stats block
#define CH 16                // HW chunks in stats

__device__ float g_stats4[B_N * K_N * CH * 4];
__device__ float g_num[K_N * NPART];
__device__ float g_den[K_N * NPART];

// ---------------------------------------------------------------------------
// Kernel 1: per-(b,k) partial sums over an HW chunk:
//   sum(labels), sum(labels*x_c) c=0..2.  4 k's per block to amortize x loads.
// ---------------------------------------------------------------------------
__global__ __launch_bounds__(256) void stats_kernel(const float* __restrict__ labels,
                                                    const float* __restrict__ inputs) {
    const int kt = blockIdx.x, b = blockIdx.y, ch = blockIdx.z, t = threadIdx.x;
    const int chunk = HW_N / CH;       // 4096 floats
    const int nf4 = chunk / 4;         // 1024 float4

    const float4* X0 = (const float4*)(inputs + (size_t)(b * 3 + 0) * HW_N + ch * chunk);
    const float4* X1 = (const float4*)(inputs + (size_t)(b * 3 + 1) * HW_N + ch * chunk);
    const float4* X2 = (const float4*)(inputs + (size_t)(b * 3 + 2) * HW_N + ch * chunk);
    const float4* L[KG];
    #pragma unroll
    for (int kk = 0; kk < KG; kk++)
        L[kk] = (const float4*)(labels + (size_t)(b * K_N + kt * KG + kk) * HW_N + ch * chunk);

    float acc[KG][4];
    #pragma unroll
    for (int kk = 0; kk < KG; kk++)
        #pragma unroll
        for (int j = 0; j < 4; j++) acc[kk][j] = 0.f;

    #pragma unroll 4
    for (int i = t; i < nf4; i += 256) {
        const float4 x0 = X0[i], x1 = X1[i], x2 = X2[i];
        #pragma unroll
        for (int kk = 0; kk < KG; kk++) {
            const float4 l = L[kk][i];
            acc[kk][0] += (l.x + l.y) + (l.z + l.w);
            acc[kk][1] = fmaf(l.x, x0.x, fmaf(l.y, x0.y, fmaf(l.z, x0.z, fmaf(l.w, x0.w, acc[kk][1]))));
            acc[kk][2] = fmaf(l.x, x1.x, fmaf(l.y, x1.y, fmaf(l.z, x1.z, fmaf(l.w, x1.w, acc[kk][2]))));
            acc[kk][3] = fmaf(l.x, x2.x, fmaf(l.y, x2.y, fmaf(l.z, x2.z, fmaf(l.w, x2.w, acc[kk][3]))));
        }
    }

    #pragma unroll
    for (int kk = 0; kk < KG; kk++)
        #pragma unroll
        for (int j = 0; j < 4; j++)
            #pragma unroll
            for (int o = 16; o; o >>= 1)
                acc[kk][j] += __shfl_down_sync(0xffffffffu, acc[kk][j], o);

    __shared__ float red[8][16];
    const int wid = t >> 5, lane = t & 31;
    if (lane == 0) {
        #pragma unroll
        for (int kk = 0; kk < KG; kk++)
            #pragma unroll
            for (int j = 0; j < 4; j++) red[wid][kk * 4 + j] = acc[kk][j];
    }
    __syncthreads();
    if (t < 16) {
        float v = 0.f;
        #pragma unroll
        for (int w = 0; w < 8; w++) v += red[w][t];
        const int k = kt * KG + (t >> 2);
        g_stats4[((b * K_N + k) * CH + ch) * 4 + (t & 3)] = v;
    }
}

// ---------------------------------------------------------------------------
// Kernel 2: adjoint-fused main pass, BARRIER-FREE main loop.
//   num_k = sum (l*w) * blur(l),  den_k = sum w * blur(l)
// h-blur: 5 overlapping L1-cached float2 loads per thread (no smem, no bar).
// v-blur: 9-deep register ring with static indices.
// Block = 128 threads = one (b,k,strip); thread owns 2 output columns.
// ---------------------------------------------------------------------------
__global__ __launch_bounds__(128) void main_kernel(const float* __restrict__ labels,
                                                   const float* __restrict__ inputs) {
    const int t = threadIdx.x;
    const int s = blockIdx.x;   // strip 0..3
    const int k = blockIdx.y;
    const int b = blockIdx.z;

    // g(d) = exp(-d^2 / (2*5^2)) -> literal immediates (FFMA-imm, rt=1)
    constexpr float G[9] = {0.72614903f, 0.83527021f, 0.92311635f, 0.98019867f, 1.0f,
                            0.98019867f, 0.92311635f, 0.83527021f, 0.72614903f};

    __shared__ float sstat[4];
    if (t < 4) {
        float v = 0.f;
        #pragma unroll
        for (int ch = 0; ch < CH; ch++)
            v += g_stats4[((b * K_N + k) * CH + ch) * 4 + t];
        sstat[t] = v;
    }
    __syncthreads();
    // class_mean_c = sumX_c / (sumL + 1e-5*HW)
    const float inv = 1.0f / (sstat[0] + 0.65536f);
    const float cm0 = sstat[1] * inv, cm1 = sstat[2] * inv, cm2 = sstat[3] * inv;

    const float* lab = labels + (size_t)(b * K_N + k) * HW_N;
    const float* xp0 = inputs + (size_t)(b * 3) * HW_N;
    const float* xp1 = xp0 + HW_N;
    const float* xp2 = xp1 + HW_N;

    const int row0 = s * STRIP_H - RAD;   // global row of padded row 0
    const int oc0 = 2 * t;                // this thread's two output columns

    // column-validity predicates for the 5 overlapping float2 loads (per-thread const)
    bool vld[5];
    #pragma unroll
    for (int i = 0; i < 5; i++) {
        const int col = oc0 - 4 + 2 * i;
        vld[i] = ((unsigned)col < (unsigned)W_N);   // col is even; col+1 also valid
    }

    float rb0[9], rb1[9];   // ring: h-blurred labels, cols oc0 / oc0+1
    float ra0[9], ra1[9];   // ring: raw center labels
    float numAcc = 0.f, denAcc = 0.f;

    for (int prb = 0; prb < PADH; prb += 9) {
        #pragma unroll
        for (int u = 0; u < 9; u++) {
            const int pr = prb + u;
            const int gr = row0 + pr;
            const bool rowOK = ((unsigned)gr < (unsigned)H_N);
            const float* rp = lab + gr * W_N + oc0;

            // --- gather 10-value horizontal window via 5 overlapping float2 LDG ---
            float v[10];
            #pragma unroll
            for (int i = 0; i < 5; i++) {
                float2 a = make_float2(0.f, 0.f);
                if (rowOK && vld[i]) a = __ldg((const float2*)(rp - 4 + 2 * i));
                v[2 * i] = a.x; v[2 * i + 1] = a.y;
            }

            // --- horizontal 9-tap ---
            float h0 = v[0] * G[0], h1 = v[1] * G[0];
            #pragma unroll
            for (int j = 1; j < 9; j++) {
                h0 = fmaf(v[j],     G[j], h0);
                h1 = fmaf(v[j + 1], G[j], h1);
            }
            rb0[u] = h0; rb1[u] = h1;          // slot pr%9 == u
            ra0[u] = v[4]; ra1[u] = v[5];      // raw labels at own cols

            // --- vertical 9-tap completes output row gor = s*64 + pr - 8 ---
            if (pr >= 8) {
                float B0 = 0.f, B1 = 0.f;
                #pragma unroll
                for (int j = 0; j < 9; j++) {
                    const int slot = (u + 1 + j) % 9;   // (pr-8+j)%9, static
                    B0 = fmaf(rb0[slot], G[j], B0);
                    B1 = fmaf(rb1[slot], G[j], B1);
                }
                const int cs = (u + 5) % 9;             // slot of row gor (pr-4)
                const float l0 = ra0[cs], l1 = ra1[cs];

                const int gor = s * STRIP_H + pr - 8;
                const int idx = gor * W_N + oc0;
                const float2 x0 = __ldg((const float2*)(xp0 + idx));
                const float2 x1 = __ldg((const float2*)(xp1 + idx));
                const float2 x2 = __ldg((const float2*)(xp2 + idx));

                const float a0 = x0.x - cm0, a1 = x1.x - cm1, a2 = x2.x - cm2;
                const float d0 = fmaf(a0, a0, fmaf(a1, a1, a2 * a2));
                const float c0 = x0.y - cm0, c1 = x1.y - cm1, c2 = x2.y - cm2;
                const float d1 = fmaf(c0, c0, fmaf(c1, c1, c2 * c2));
                const float w0 = __expf(-d0 * d0);
                const float w1 = __expf(-d1 * d1);

                numAcc = fmaf(l0 * w0, B0, numAcc);
                numAcc = fmaf(l1 * w1, B1, numAcc);
                denAcc = fmaf(w0, B0, denAcc);
                denAcc = fmaf(w1, B1, denAcc);
            }
        }
    }

    // --- deterministic block reduction ---
    #pragma unroll
    for (int o = 16; o; o >>= 1) {
        numAcc += __shfl_down_sync(0xffffffffu, numAcc, o);
        denAcc += __shfl_down_sync(0xffffffffu, denAcc, o);
    }
    __shared__ float rn[4], rd[4];
    if ((t & 31) == 0) { rn[t >> 5] = numAcc; rd[t >> 5] = denAcc; }
    __syncthreads();
    if (t == 0) {
        const float n = (rn[0] + rn[1]) + (rn[2] + rn[3]);
        const float d = (rd[0] + rd[1]) + (rd[2] + rd[3]);
        const int idx = (k * B_N + b) * NSTRIP + s;
        g_num[idx] = n;
        g_den[idx] = d;
    }
}

// ---------------------------------------------------------------------------
// Kernel 3: final deterministic reduction -> scalar loss
// ---------------------------------------------------------------------------
__global__ void finish_kernel(float* __restrict__ out) {
    __shared__ float sv[K_N];
    const int t = threadIdx.x;
    if (t < K_N) {
        float n = 0.f, d = 0.f;
        for (int i = 0; i < NPART; i++) {
            n += g_num[t * NPART + i];
            d += g_den[t * NPART + i];
        }
        sv[t] = fabsf(n / (d + 1e-6f));
    }
    __syncthreads();
    if (t == 0) {
        float loss = 0.f;
        for (int i = 0; i < K_N; i++) loss += sv[i];
        out[0] = (float)K_N - loss;
    }
}

// ---------------------------------------------------------------------------
extern "C" void kernel_launch(void* const* d_in, const int* in_sizes, int n_in,
                              void* d_out, int out_size) {
    (void)n_in; (void)out_size;
    const float* labels;
    const float* inputs;
    if (in_sizes[0] == B_N * K_N * HW_N) {
        labels = (const float*)d_in[0];
        inputs = (const float*)d_in[1];
    } else {
        labels = (const float*)d_in[1];
        inputs = (const float*)d_in[0];
    }
    float* out = (float*)d_out;

    stats_kernel<<<dim3(K_N / KG, B_N, CH), 256>>>(labels, inputs);
    main_kernel<<<dim3(NSTRIP, K_N, B_N), 128>>>(labels, inputs);
    finish_kernel<<<1, 32>>>(out);
}